// round 15
// baseline (speedup 1.0000x reference)
#include <cuda_runtime.h>
#include <cuda_bf16.h>
#include <cuda_fp16.h>
#include <math.h>
#include <cstdint>

#define BATCHSZ 64
#define SEQLEN  512
#define ISZ     512
#define HSZ     1024
#define GHSZ    4096
#define NBLK    128

// ================= device scratch =================
__device__ float g_xg[(size_t)SEQLEN * BATCHSZ * GHSZ];      // [S][B][4H]
__device__ unsigned g_bar;
__device__ __align__(16) __half g_xhi[(size_t)BATCHSZ * SEQLEN * ISZ];
__device__ __align__(16) __half g_wthi[(size_t)GHSZ * ISZ];   // WxT [n][k]
__device__ __align__(16) __half g_wtlo[(size_t)GHSZ * ISZ];
__device__ __align__(16) __half g_whh[(size_t)NBLK * 32 * HSZ];   // Wh fp16 [blk][nl][k]
__device__ __align__(16) __half g_hh[2][BATCHSZ * HSZ];           // h fp16, double buffered

// ================= helpers =================
__device__ __forceinline__ uint32_t smem_u32(const void* p) {
    uint32_t a;
    asm("{ .reg .u64 t; cvta.to.shared.u64 t, %1; cvt.u32.u64 %0, t; }" : "=r"(a) : "l"(p));
    return a;
}

#define LDSM_X4(r0, r1, r2, r3, addr)                                        \
    asm volatile("ldmatrix.sync.aligned.m8n8.x4.shared.b16 {%0,%1,%2,%3}, [%4];" \
                 : "=r"(r0), "=r"(r1), "=r"(r2), "=r"(r3) : "r"(addr))

#define MMAF16(c, a, b)                                                      \
    asm volatile("mma.sync.aligned.m16n8k16.row.col.f32.f16.f16.f32 "        \
                 "{%0,%1,%2,%3}, {%4,%5,%6,%7}, {%8,%9}, {%0,%1,%2,%3};"     \
                 : "+f"((c)[0]), "+f"((c)[1]), "+f"((c)[2]), "+f"((c)[3])    \
                 : "r"((a)[0]), "r"((a)[1]), "r"((a)[2]), "r"((a)[3]),       \
                   "r"((b)[0]), "r"((b)[1]))

#define CP_ASYNC16(smaddr, gptr)                                             \
    asm volatile("cp.async.cg.shared.global [%0], [%1], 16;"                 \
                 :: "r"(smaddr), "l"(__cvta_generic_to_global(gptr)) : "memory")
#define CP_COMMIT()  asm volatile("cp.async.commit_group;" ::: "memory")
#define CP_WAIT0()   asm volatile("cp.async.wait_group 0;" ::: "memory")
#define CP_WAIT1()   asm volatile("cp.async.wait_group 1;" ::: "memory")

__device__ __forceinline__ float sigmoidf_(float v) { return 1.f / (1.f + __expf(-v)); }

// ================= fused prep kernel =================
__global__ void prep(const float* __restrict__ x,
                     const float* __restrict__ Wx,
                     const float* __restrict__ Wh) {
    int bid = blockIdx.x;
    if (bid < 16384) {
        size_t i = ((size_t)bid * 256 + threadIdx.x) * 4;
        float4 v = *(const float4*)(x + i);
        __half2* hp = (__half2*)(g_xhi + i);
        hp[0] = __half2(__float2half_rn(v.x), __float2half_rn(v.y));
        hp[1] = __half2(__float2half_rn(v.z), __float2half_rn(v.w));
    } else if (bid < 24576) {
        int i = (bid - 16384) * 256 + threadIdx.x;   // 4*512*1024
        int g = i >> 19;
        int r = i & 524287;
        int k = r >> 10;
        int h = r & 1023;
        float v = Wx[i];
        __half hi = __float2half_rn(v);
        __half lo = __float2half_rn(v - __half2float(hi));
        size_t o = (size_t)(g * HSZ + h) * ISZ + k;
        g_wthi[o] = hi;
        g_wtlo[o] = lo;
    } else {
        int d = (bid - 24576) * 256 + threadIdx.x;   // 4M
        int k   = d & 1023;
        int nl  = (d >> 10) & 31;
        int blk = d >> 15;
        int g   = nl >> 3;
        int h   = blk * 8 + (nl & 7);
        g_whh[d] = __float2half_rn(Wh[(size_t)g * HSZ * HSZ + (size_t)k * HSZ + h]);
    }
}

__global__ void init_bar() { if (threadIdx.x == 0) g_bar = 0u; }

// ================= phase 1: pipelined mma.sync GEMM, 2 products (unchanged) =================
#define TILE_B   8192
#define GX_STAGE 24576
#define GX_SMEM  (3 * GX_STAGE)

__global__ __launch_bounds__(256, 2) void gemm_x_mma(const float* __restrict__ bias) {
    extern __shared__ char gsm[];

    const int tid  = threadIdx.x;
    const int lane = tid & 31;
    const int wid  = tid >> 5;
    const int wm   = (wid & 1) * 64;
    const int wn   = (wid >> 1) * 32;
    const int m0   = blockIdx.y * 128;
    const int j0   = blockIdx.x * 128;

    const uint32_t sb = smem_u32(gsm);
    const int g = lane >> 3;
    const int r = lane & 7;

    float acc[4][4][4];
#pragma unroll
    for (int mi = 0; mi < 4; mi++)
#pragma unroll
        for (int ni = 0; ni < 4; ni++)
#pragma unroll
            for (int e = 0; e < 4; e++) acc[mi][ni][e] = 0.f;

#define GX_STAGE_CHUNK(s) do {                                               \
    int k0_ = (s) * 32;                                                      \
    uint32_t db_ = sb + ((s) % 3) * GX_STAGE;                                \
    _Pragma("unroll")                                                        \
    for (int l_ = 0; l_ < 2; l_++) {                                         \
        int u_ = tid + l_ * 256;                                             \
        int row_ = u_ >> 2, ch_ = u_ & 3;                                    \
        uint32_t so_ = row_ * 64 + ((ch_ ^ ((row_ >> 1) & 3)) << 4);         \
        size_t ga_ = (size_t)(m0 + row_) * ISZ + k0_ + ch_ * 8;              \
        size_t gb_ = (size_t)(j0 + row_) * ISZ + k0_ + ch_ * 8;              \
        CP_ASYNC16(db_ + so_,              g_xhi + ga_);                     \
        CP_ASYNC16(db_ + TILE_B + so_,     g_wthi + gb_);                    \
        CP_ASYNC16(db_ + 2 * TILE_B + so_, g_wtlo + gb_);                    \
    }                                                                        \
} while (0)

#pragma unroll
    for (int ps = 0; ps < 2; ps++) {
        GX_STAGE_CHUNK(ps);
        CP_COMMIT();
    }

    for (int s = 0; s < 16; s++) {
        CP_WAIT1();
        __syncthreads();

        const uint32_t stb = sb + (s % 3) * GX_STAGE;
#pragma unroll
        for (int s2 = 0; s2 < 2; s2++) {
            uint32_t ahi[4][4];
#pragma unroll
            for (int mi = 0; mi < 4; mi++) {
                int row = wm + mi * 16 + (g & 1) * 8 + r;
                int ch  = (s2 * 2 + (g >> 1)) ^ ((row >> 1) & 3);
                uint32_t ad = stb + row * 64 + ch * 16;
                LDSM_X4(ahi[mi][0], ahi[mi][1], ahi[mi][2], ahi[mi][3], ad);
            }
            uint32_t bhi[4][2], blo[4][2];
#pragma unroll
            for (int nb = 0; nb < 2; nb++) {
                int row = wn + nb * 16 + (g >> 1) * 8 + r;
                int ch  = (s2 * 2 + (g & 1)) ^ ((row >> 1) & 3);
                uint32_t bd = stb + TILE_B + row * 64 + ch * 16;
                LDSM_X4(bhi[nb * 2][0], bhi[nb * 2][1],
                        bhi[nb * 2 + 1][0], bhi[nb * 2 + 1][1], bd);
                LDSM_X4(blo[nb * 2][0], blo[nb * 2][1],
                        blo[nb * 2 + 1][0], blo[nb * 2 + 1][1], bd + TILE_B);
            }
#pragma unroll
            for (int mi = 0; mi < 4; mi++)
#pragma unroll
                for (int ni = 0; ni < 4; ni++) {
                    MMAF16(acc[mi][ni], ahi[mi], bhi[ni]);
                    MMAF16(acc[mi][ni], ahi[mi], blo[ni]);
                }
        }

        if (s + 2 < 16) GX_STAGE_CHUNK(s + 2);
        CP_COMMIT();
    }

    const int r4 = lane >> 2;
    const int c2 = (lane & 3) * 2;
#pragma unroll
    for (int mi = 0; mi < 4; mi++) {
        int mA = m0 + wm + mi * 16 + r4;
        int mB = mA + 8;
        size_t baseA = (((size_t)((mA & 511) * BATCHSZ + (mA >> 9))) << 12);
        size_t baseB = (((size_t)((mB & 511) * BATCHSZ + (mB >> 9))) << 12);
#pragma unroll
        for (int ni = 0; ni < 4; ni++) {
            int n = j0 + wn + ni * 8 + c2;
            float2 bv = *(const float2*)(bias + n);
            float2 vA = make_float2(acc[mi][ni][0] + bv.x, acc[mi][ni][1] + bv.y);
            float2 vB = make_float2(acc[mi][ni][2] + bv.x, acc[mi][ni][3] + bv.y);
            *(float2*)(g_xg + baseA + n) = vA;
            *(float2*)(g_xg + baseB + n) = vB;
        }
    }
}

// ================= phase 2: persistent mma LSTM scan (W fp16, k256 slabs) =================
// smem: W tiles [16 k64-slabs][32n x 128B]  = 64KB at 0
//       h ring  [2 buf][32KB (64r x 512B)]  = 64KB at 65536
//       red     [512 rows x 34 floats]      = 68KB at 131072  (stride 34: conflict-free)
//       c_sm    [512] float                         at 200704
#define WOFF 0
#define HOFF 65536
#define ROFF 131072
#define COFF 200704
#define SCAN_SMEM (200704 + 2048)
#define STHR 512

#define GRID_BARRIER(target) do {                                            \
    __syncthreads();                                                         \
    if (tid == 0) {                                                          \
        __threadfence();                                                     \
        atomicAdd(&g_bar, 1u);                                               \
        unsigned v_;                                                         \
        do {                                                                 \
            asm volatile("ld.acquire.gpu.u32 %0, [%1];" : "=r"(v_) : "l"(&g_bar) : "memory"); \
        } while (v_ < (unsigned)(target));                                   \
    }                                                                        \
    __syncthreads();                                                         \
} while (0)

__global__ __launch_bounds__(STHR, 1) void lstm_scan(float* __restrict__ out) {
    extern __shared__ char sm[];
    const uint32_t sb = smem_u32(sm);
    float* c_sm = (float*)(sm + COFF);
    float* red  = (float*)(sm + ROFF);

    const int tid  = threadIdx.x;
    const int blk  = blockIdx.x;
    const int h0   = blk * 8;
    const int lane = tid & 31, wid = tid >> 5;
    const int wm   = wid & 1;             // M half (batches 0-31 / 32-63)
    const int ks   = wid >> 1;            // pair-of-k16 slot within k256 slab (0..7)
    const int g8   = lane >> 3, r8 = lane & 7;

    // zero own h columns (buf 0) + c
    {
        int b = tid >> 3, hl = tid & 7;
        g_hh[0][b * HSZ + h0 + hl] = __float2half(0.f);
        c_sm[tid] = 0.f;
    }

    // load W into smem once: 4096 16B-chunks / 512 threads (fp16, no lo)
#pragma unroll
    for (int l = 0; l < 8; l++) {
        int u = tid + l * STHR;
        int tile = u >> 8;                // k64 slab 0..15
        int c = u & 255;
        int row = c >> 3, cc = c & 7;
        const __half* src = g_whh + ((size_t)(blk * 32 + row) * HSZ + tile * 64 + cc * 8);
        *(uint4*)(sm + WOFF + tile * 4096 + row * 128 + ((cc ^ (row & 7)) << 4))
            = *(const uint4*)src;
    }

    GRID_BARRIER(NBLK);   // zeros + W visible

    // epilogue mapping: thread owns 1 (b,hl) pair
    const int bp = tid >> 3, hlp = tid & 7;

    // h-slab staging: k256 slab (64 rows x 512B = 32KB) -> ring buffer slab&1
#define SCAN_STAGE(slab) do {                                                \
    uint32_t hb_ = sb + HOFF + ((slab) & 1) * 32768;                         \
    _Pragma("unroll")                                                        \
    for (int l_ = 0; l_ < 4; l_++) {                                         \
        int u_ = tid + l_ * STHR;                                            \
        int row_ = u_ >> 5, cc_ = u_ & 31;                                   \
        uint32_t d_ = hb_ + row_ * 512 + ((cc_ ^ (row_ & 7)) << 4);          \
        CP_ASYNC16(d_, hh + row_ * HSZ + (slab) * 256 + cc_ * 8);            \
    }                                                                        \
} while (0)

    for (int t = 0; t < SEQLEN; t++) {
        const __half* hh = g_hh[t & 1];

        // prefetch xg for epilogue
        float xq[4];
        {
            size_t base = (((size_t)(t * BATCHSZ + bp)) << 12) + h0 + hlp;
#pragma unroll
            for (int g = 0; g < 4; g++) xq[g] = __ldcs(&g_xg[base + (size_t)g * HSZ]);
        }

        float acc[2][4][4];
#pragma unroll
        for (int mi = 0; mi < 2; mi++)
#pragma unroll
            for (int ni = 0; ni < 4; ni++)
#pragma unroll
                for (int e = 0; e < 4; e++) acc[mi][ni][e] = 0.f;

        // prologue: slab 0
        SCAN_STAGE(0);
        CP_COMMIT();

        for (int s = 0; s < 4; s++) {
            if (s < 3) {
                SCAN_STAGE(s + 1);
                CP_COMMIT();
                CP_WAIT1();
            } else {
                CP_WAIT0();
            }
            __syncthreads();

            // ---- compute slab s: this warp's k16s = s*16 + ks*2 + {0,1} ----
            uint32_t hb = sb + HOFF + (s & 1) * 32768;
            uint32_t ah[2][2][4], bh[2][4][2];
#pragma unroll
            for (int mi = 0; mi < 2; mi++) {
                int row = wm * 32 + mi * 16 + (g8 & 1) * 8 + r8;
#pragma unroll
                for (int kc = 0; kc < 2; kc++) {
                    int cc = (ks * 2 + kc) * 2 + (g8 >> 1);   // chunk within 512B row
                    uint32_t ad = hb + row * 512 + (((cc ^ (row & 7))) << 4);
                    LDSM_X4(ah[mi][kc][0], ah[mi][kc][1], ah[mi][kc][2], ah[mi][kc][3], ad);
                }
            }
#pragma unroll
            for (int kc = 0; kc < 2; kc++) {
                int kk = s * 16 + ks * 2 + kc;
                int sW = kk >> 2, c4 = kk & 3;
#pragma unroll
                for (int nb = 0; nb < 2; nb++) {
                    int row = nb * 16 + (g8 >> 1) * 8 + r8;
                    int cc2 = c4 * 2 + (g8 & 1);
                    uint32_t bd = sb + WOFF + sW * 4096 + row * 128 + (((cc2 ^ (row & 7))) << 4);
                    LDSM_X4(bh[kc][nb * 2][0], bh[kc][nb * 2][1],
                            bh[kc][nb * 2 + 1][0], bh[kc][nb * 2 + 1][1], bd);
                }
            }
#pragma unroll
            for (int kc = 0; kc < 2; kc++)
#pragma unroll
                for (int mi = 0; mi < 2; mi++)
#pragma unroll
                    for (int ni = 0; ni < 4; ni++)
                        MMAF16(acc[mi][ni], ah[mi][kc], bh[kc][ni]);

            __syncthreads();   // buffer (s&1) free for slab s+2's staging
        }

        // ---- write K-partials: red[(ks*64 + b)*34 + n] (stride 34: conflict-free) ----
#pragma unroll
        for (int mi = 0; mi < 2; mi++) {
            int b = wm * 32 + mi * 16 + (lane >> 2);
            int n = (lane & 3) * 2;
            float* rr = red + (ks * 64 + b) * 34 + n;
#pragma unroll
            for (int ni = 0; ni < 4; ni++)
                *(float2*)(rr + ni * 8) = make_float2(acc[mi][ni][0], acc[mi][ni][1]);
            float* rr2 = red + (ks * 64 + b + 8) * 34 + n;
#pragma unroll
            for (int ni = 0; ni < 4; ni++)
                *(float2*)(rr2 + ni * 8) = make_float2(acc[mi][ni][2], acc[mi][ni][3]);
        }
        __syncthreads();

        // ---- cell update: 1 (b,hl) pair per thread ----
        {
            float sg[4];
#pragma unroll
            for (int g = 0; g < 4; g++) {
                int n = g * 8 + hlp;
                float s0 = 0.f;
#pragma unroll
                for (int k2 = 0; k2 < 8; k2++)
                    s0 += red[(k2 * 64 + bp) * 34 + n];
                sg[g] = s0 + xq[g];
            }
            float gi = sigmoidf_(sg[0]);
            float gf = sigmoidf_(sg[1]);
            float gg = tanhf(sg[2]);
            float go = sigmoidf_(sg[3]);
            float cn = gf * c_sm[tid] + gi * gg;
            c_sm[tid] = cn;
            float hn = go * tanhf(cn);
            if (t < SEQLEN - 1) {
                g_hh[(t + 1) & 1][bp * HSZ + h0 + hlp] = __float2half_rn(hn);
            } else {
                out[bp * HSZ + h0 + hlp] = hn;
                out[BATCHSZ * HSZ + bp * HSZ + h0 + hlp] = cn;
            }
        }

        if (t < SEQLEN - 1) {
            GRID_BARRIER((t + 2) * NBLK);
        }
    }
}

// ================= launch =================
extern "C" void kernel_launch(void* const* d_in, const int* in_sizes, int n_in,
                              void* d_out, int out_size) {
    const float* x    = (const float*)d_in[0];
    const float* Wx   = (const float*)d_in[1];
    const float* Wh   = (const float*)d_in[2];
    const float* bias = (const float*)d_in[3];
    float* out = (float*)d_out;

    cudaFuncSetAttribute(lstm_scan, cudaFuncAttributeMaxDynamicSharedMemorySize, SCAN_SMEM);
    cudaFuncSetAttribute(gemm_x_mma, cudaFuncAttributeMaxDynamicSharedMemorySize, GX_SMEM);

    init_bar<<<1, 32>>>();                 // zero barrier counter (every graph replay)
    prep<<<40960, 256>>>(x, Wx, Wh);       // slot 1

    dim3 g1(GHSZ / 128, (BATCHSZ * SEQLEN) / 128);
    gemm_x_mma<<<g1, 256, GX_SMEM>>>(bias);  // slot 2

    lstm_scan<<<NBLK, STHR, SCAN_SMEM>>>(out);  // slot 3 -> ncu capture window
}

// round 16
// speedup vs baseline: 1.0646x; 1.0646x over previous
#include <cuda_runtime.h>
#include <cuda_bf16.h>
#include <cuda_fp16.h>
#include <math.h>
#include <cstdint>

#define BATCHSZ 64
#define SEQLEN  512
#define ISZ     512
#define HSZ     1024
#define GHSZ    4096
#define NBLK    128

// ================= device scratch =================
__device__ float g_xg[(size_t)SEQLEN * BATCHSZ * GHSZ];      // [S][B][4H]
__device__ unsigned g_bar;
__device__ __align__(16) __half g_xhi[(size_t)BATCHSZ * SEQLEN * ISZ];
__device__ __align__(16) __half g_wthi[(size_t)GHSZ * ISZ];   // WxT [n][k]
__device__ __align__(16) __half g_wtlo[(size_t)GHSZ * ISZ];
__device__ __align__(16) __half g_whh[(size_t)NBLK * 32 * HSZ];   // Wh fp16 [blk][nl][k]
__device__ __align__(16) __half g_hh[2][BATCHSZ * HSZ];           // h fp16, double buffered

// ================= helpers =================
__device__ __forceinline__ uint32_t smem_u32(const void* p) {
    uint32_t a;
    asm("{ .reg .u64 t; cvta.to.shared.u64 t, %1; cvt.u32.u64 %0, t; }" : "=r"(a) : "l"(p));
    return a;
}

#define LDSM_X4(r0, r1, r2, r3, addr)                                        \
    asm volatile("ldmatrix.sync.aligned.m8n8.x4.shared.b16 {%0,%1,%2,%3}, [%4];" \
                 : "=r"(r0), "=r"(r1), "=r"(r2), "=r"(r3) : "r"(addr))

#define MMAF16(c, a, b)                                                      \
    asm volatile("mma.sync.aligned.m16n8k16.row.col.f32.f16.f16.f32 "        \
                 "{%0,%1,%2,%3}, {%4,%5,%6,%7}, {%8,%9}, {%0,%1,%2,%3};"     \
                 : "+f"((c)[0]), "+f"((c)[1]), "+f"((c)[2]), "+f"((c)[3])    \
                 : "r"((a)[0]), "r"((a)[1]), "r"((a)[2]), "r"((a)[3]),       \
                   "r"((b)[0]), "r"((b)[1]))

#define CP_ASYNC16(smaddr, gptr)                                             \
    asm volatile("cp.async.cg.shared.global [%0], [%1], 16;"                 \
                 :: "r"(smaddr), "l"(__cvta_generic_to_global(gptr)) : "memory")
#define CP_COMMIT()  asm volatile("cp.async.commit_group;" ::: "memory")
#define CP_WAIT0()   asm volatile("cp.async.wait_group 0;" ::: "memory")
#define CP_WAIT1()   asm volatile("cp.async.wait_group 1;" ::: "memory")

__device__ __forceinline__ float sigmoidf_(float v) { return 1.f / (1.f + __expf(-v)); }

// ================= fused prep kernel =================
__global__ void prep(const float* __restrict__ x,
                     const float* __restrict__ Wx,
                     const float* __restrict__ Wh) {
    int bid = blockIdx.x;
    if (bid < 16384) {
        size_t i = ((size_t)bid * 256 + threadIdx.x) * 4;
        float4 v = *(const float4*)(x + i);
        __half2* hp = (__half2*)(g_xhi + i);
        hp[0] = __half2(__float2half_rn(v.x), __float2half_rn(v.y));
        hp[1] = __half2(__float2half_rn(v.z), __float2half_rn(v.w));
    } else if (bid < 24576) {
        int i = (bid - 16384) * 256 + threadIdx.x;   // 4*512*1024
        int g = i >> 19;
        int r = i & 524287;
        int k = r >> 10;
        int h = r & 1023;
        float v = Wx[i];
        __half hi = __float2half_rn(v);
        __half lo = __float2half_rn(v - __half2float(hi));
        size_t o = (size_t)(g * HSZ + h) * ISZ + k;
        g_wthi[o] = hi;
        g_wtlo[o] = lo;
    } else {
        int d = (bid - 24576) * 256 + threadIdx.x;   // 4M
        int k   = d & 1023;
        int nl  = (d >> 10) & 31;
        int blk = d >> 15;
        int g   = nl >> 3;
        int h   = blk * 8 + (nl & 7);
        g_whh[d] = __float2half_rn(Wh[(size_t)g * HSZ * HSZ + (size_t)k * HSZ + h]);
    }
}

__global__ void init_bar() { if (threadIdx.x == 0) g_bar = 0u; }

// ================= phase 1: pipelined mma.sync GEMM, 2 products (unchanged) =================
#define TILE_B   8192
#define GX_STAGE 24576
#define GX_SMEM  (3 * GX_STAGE)

__global__ __launch_bounds__(256, 2) void gemm_x_mma(const float* __restrict__ bias) {
    extern __shared__ char gsm[];

    const int tid  = threadIdx.x;
    const int lane = tid & 31;
    const int wid  = tid >> 5;
    const int wm   = (wid & 1) * 64;
    const int wn   = (wid >> 1) * 32;
    const int m0   = blockIdx.y * 128;
    const int j0   = blockIdx.x * 128;

    const uint32_t sb = smem_u32(gsm);
    const int g = lane >> 3;
    const int r = lane & 7;

    float acc[4][4][4];
#pragma unroll
    for (int mi = 0; mi < 4; mi++)
#pragma unroll
        for (int ni = 0; ni < 4; ni++)
#pragma unroll
            for (int e = 0; e < 4; e++) acc[mi][ni][e] = 0.f;

#define GX_STAGE_CHUNK(s) do {                                               \
    int k0_ = (s) * 32;                                                      \
    uint32_t db_ = sb + ((s) % 3) * GX_STAGE;                                \
    _Pragma("unroll")                                                        \
    for (int l_ = 0; l_ < 2; l_++) {                                         \
        int u_ = tid + l_ * 256;                                             \
        int row_ = u_ >> 2, ch_ = u_ & 3;                                    \
        uint32_t so_ = row_ * 64 + ((ch_ ^ ((row_ >> 1) & 3)) << 4);         \
        size_t ga_ = (size_t)(m0 + row_) * ISZ + k0_ + ch_ * 8;              \
        size_t gb_ = (size_t)(j0 + row_) * ISZ + k0_ + ch_ * 8;              \
        CP_ASYNC16(db_ + so_,              g_xhi + ga_);                     \
        CP_ASYNC16(db_ + TILE_B + so_,     g_wthi + gb_);                    \
        CP_ASYNC16(db_ + 2 * TILE_B + so_, g_wtlo + gb_);                    \
    }                                                                        \
} while (0)

#pragma unroll
    for (int ps = 0; ps < 2; ps++) {
        GX_STAGE_CHUNK(ps);
        CP_COMMIT();
    }

    for (int s = 0; s < 16; s++) {
        CP_WAIT1();
        __syncthreads();

        const uint32_t stb = sb + (s % 3) * GX_STAGE;
#pragma unroll
        for (int s2 = 0; s2 < 2; s2++) {
            uint32_t ahi[4][4];
#pragma unroll
            for (int mi = 0; mi < 4; mi++) {
                int row = wm + mi * 16 + (g & 1) * 8 + r;
                int ch  = (s2 * 2 + (g >> 1)) ^ ((row >> 1) & 3);
                uint32_t ad = stb + row * 64 + ch * 16;
                LDSM_X4(ahi[mi][0], ahi[mi][1], ahi[mi][2], ahi[mi][3], ad);
            }
            uint32_t bhi[4][2], blo[4][2];
#pragma unroll
            for (int nb = 0; nb < 2; nb++) {
                int row = wn + nb * 16 + (g >> 1) * 8 + r;
                int ch  = (s2 * 2 + (g & 1)) ^ ((row >> 1) & 3);
                uint32_t bd = stb + TILE_B + row * 64 + ch * 16;
                LDSM_X4(bhi[nb * 2][0], bhi[nb * 2][1],
                        bhi[nb * 2 + 1][0], bhi[nb * 2 + 1][1], bd);
                LDSM_X4(blo[nb * 2][0], blo[nb * 2][1],
                        blo[nb * 2 + 1][0], blo[nb * 2 + 1][1], bd + TILE_B);
            }
#pragma unroll
            for (int mi = 0; mi < 4; mi++)
#pragma unroll
                for (int ni = 0; ni < 4; ni++) {
                    MMAF16(acc[mi][ni], ahi[mi], bhi[ni]);
                    MMAF16(acc[mi][ni], ahi[mi], blo[ni]);
                }
        }

        if (s + 2 < 16) GX_STAGE_CHUNK(s + 2);
        CP_COMMIT();
    }

    const int r4 = lane >> 2;
    const int c2 = (lane & 3) * 2;
#pragma unroll
    for (int mi = 0; mi < 4; mi++) {
        int mA = m0 + wm + mi * 16 + r4;
        int mB = mA + 8;
        size_t baseA = (((size_t)((mA & 511) * BATCHSZ + (mA >> 9))) << 12);
        size_t baseB = (((size_t)((mB & 511) * BATCHSZ + (mB >> 9))) << 12);
#pragma unroll
        for (int ni = 0; ni < 4; ni++) {
            int n = j0 + wn + ni * 8 + c2;
            float2 bv = *(const float2*)(bias + n);
            float2 vA = make_float2(acc[mi][ni][0] + bv.x, acc[mi][ni][1] + bv.y);
            float2 vB = make_float2(acc[mi][ni][2] + bv.x, acc[mi][ni][3] + bv.y);
            *(float2*)(g_xg + baseA + n) = vA;
            *(float2*)(g_xg + baseB + n) = vB;
        }
    }
}

// ================= phase 2: persistent mma LSTM scan (W fp16, k512 slabs) =================
// smem: W tiles [16 k64-slabs][32n x 128B]   = 64KB at 0
//       h ring  [2 buf][64KB (64r x 1024B)]  = 128KB at 65536
//       red     [512 rows x 32 floats] = 64KB, ALIASES ring buf0 (safe: see syncs)
//       c_sm    [512] float                          at 196608
#define WOFF 0
#define HOFF 65536
#define COFF 196608
#define SCAN_SMEM (196608 + 2048)
#define STHR 512

#define GRID_BARRIER(target) do {                                            \
    __syncthreads();                                                         \
    if (tid == 0) {                                                          \
        __threadfence();                                                     \
        atomicAdd(&g_bar, 1u);                                               \
        unsigned v_;                                                         \
        do {                                                                 \
            asm volatile("ld.acquire.gpu.u32 %0, [%1];" : "=r"(v_) : "l"(&g_bar) : "memory"); \
        } while (v_ < (unsigned)(target));                                   \
    }                                                                        \
    __syncthreads();                                                         \
} while (0)

__global__ __launch_bounds__(STHR, 1) void lstm_scan(float* __restrict__ out) {
    extern __shared__ char sm[];
    const uint32_t sb = smem_u32(sm);
    float* c_sm = (float*)(sm + COFF);
    float* red  = (float*)(sm + HOFF);    // 64KB, aliases ring buffer 0

    const int tid  = threadIdx.x;
    const int blk  = blockIdx.x;
    const int h0   = blk * 8;
    const int lane = tid & 31, wid = tid >> 5;
    const int wm   = wid & 1;             // M half (batches 0-31 / 32-63)
    const int ks   = wid >> 1;            // k64 slot within k512 slab (0..7)
    const int g8   = lane >> 3, r8 = lane & 7;

    // zero own h columns (buf 0) + c
    {
        int b = tid >> 3, hl = tid & 7;
        g_hh[0][b * HSZ + h0 + hl] = __float2half(0.f);
        c_sm[tid] = 0.f;
    }

    // load W into smem once: 4096 16B-chunks / 512 threads (fp16)
#pragma unroll
    for (int l = 0; l < 8; l++) {
        int u = tid + l * STHR;
        int tile = u >> 8;                // k64 tile 0..15
        int c = u & 255;
        int row = c >> 3, cc = c & 7;
        const __half* src = g_whh + ((size_t)(blk * 32 + row) * HSZ + tile * 64 + cc * 8);
        *(uint4*)(sm + WOFF + tile * 4096 + row * 128 + ((cc ^ (row & 7)) << 4))
            = *(const uint4*)src;
    }

    GRID_BARRIER(NBLK);   // zeros + W visible

    // epilogue mapping: thread owns 1 (b,hl) pair
    const int bp = tid >> 3, hlp = tid & 7;

    // h-slab staging: k512 slab (64 rows x 1024B = 64KB) -> ring buffer slab&1
#define SCAN_STAGE(slab) do {                                                \
    uint32_t hb_ = sb + HOFF + ((slab) & 1) * 65536;                         \
    _Pragma("unroll")                                                        \
    for (int l_ = 0; l_ < 8; l_++) {                                         \
        int u_ = tid + l_ * STHR;                                            \
        int row_ = u_ >> 6, cc_ = u_ & 63;                                   \
        uint32_t d_ = hb_ + row_ * 1024 + ((cc_ ^ (row_ & 7)) << 4);         \
        CP_ASYNC16(d_, hh + row_ * HSZ + (slab) * 512 + cc_ * 8);            \
    }                                                                        \
} while (0)

    for (int t = 0; t < SEQLEN; t++) {
        const __half* hh = g_hh[t & 1];

        // prefetch xg for epilogue
        float xq[4];
        {
            size_t base = (((size_t)(t * BATCHSZ + bp)) << 12) + h0 + hlp;
#pragma unroll
            for (int g = 0; g < 4; g++) xq[g] = __ldcs(&g_xg[base + (size_t)g * HSZ]);
        }

        float acc[2][4][4];
#pragma unroll
        for (int mi = 0; mi < 2; mi++)
#pragma unroll
            for (int ni = 0; ni < 4; ni++)
#pragma unroll
                for (int e = 0; e < 4; e++) acc[mi][ni][e] = 0.f;

        // prologue: slab 0
        SCAN_STAGE(0);
        CP_COMMIT();

#pragma unroll
        for (int s = 0; s < 2; s++) {
            if (s == 0) {
                SCAN_STAGE(1);
                CP_COMMIT();
                CP_WAIT1();        // slab 0 landed
            } else {
                CP_WAIT0();        // slab 1 landed
            }
            __syncthreads();       // block-wide visibility of slab s

            // ---- compute slab s: this warp's k16s = s*32 + ks*4 + {0..3} ----
            uint32_t hb = sb + HOFF + (s & 1) * 65536;
#pragma unroll
            for (int half = 0; half < 2; half++) {
                uint32_t ah[2][2][4], bh[2][4][2];
#pragma unroll
                for (int mi = 0; mi < 2; mi++) {
                    int row = wm * 32 + mi * 16 + (g8 & 1) * 8 + r8;
#pragma unroll
                    for (int kc = 0; kc < 2; kc++) {
                        int kks = ks * 4 + half * 2 + kc;      // k16 within slab (0..31)
                        int cc  = kks * 2 + (g8 >> 1);          // 16B chunk in 1024B row
                        uint32_t ad = hb + row * 1024 + (((cc ^ (row & 7))) << 4);
                        LDSM_X4(ah[mi][kc][0], ah[mi][kc][1], ah[mi][kc][2], ah[mi][kc][3], ad);
                    }
                }
#pragma unroll
                for (int kc = 0; kc < 2; kc++) {
                    int kk = s * 32 + ks * 4 + half * 2 + kc;   // global k16 (0..63)
                    int sW = kk >> 2, c4 = kk & 3;
#pragma unroll
                    for (int nb = 0; nb < 2; nb++) {
                        int row = nb * 16 + (g8 >> 1) * 8 + r8;
                        int cc2 = c4 * 2 + (g8 & 1);
                        uint32_t bd = sb + WOFF + sW * 4096 + row * 128 + (((cc2 ^ (row & 7))) << 4);
                        LDSM_X4(bh[kc][nb * 2][0], bh[kc][nb * 2][1],
                                bh[kc][nb * 2 + 1][0], bh[kc][nb * 2 + 1][1], bd);
                    }
                }
#pragma unroll
                for (int kc = 0; kc < 2; kc++)
#pragma unroll
                    for (int mi = 0; mi < 2; mi++)
#pragma unroll
                        for (int ni = 0; ni < 4; ni++)
                            MMAF16(acc[mi][ni], ah[mi][kc], bh[kc][ni]);
            }
            // no trailing sync: within a step no buffer is restaged; buf0 reads
            // are ordered before red writes by slab 1's top-of-iteration sync.
        }

        // ---- write K-partials to red (aliases buf0; safe per sync above) ----
#pragma unroll
        for (int mi = 0; mi < 2; mi++) {
            int b = wm * 32 + mi * 16 + (lane >> 2);
            int n = (lane & 3) * 2;
            float* rr = red + (ks * 64 + b) * 32 + n;
#pragma unroll
            for (int ni = 0; ni < 4; ni++)
                *(float2*)(rr + ni * 8) = make_float2(acc[mi][ni][0], acc[mi][ni][1]);
            float* rr2 = red + (ks * 64 + b + 8) * 32 + n;
#pragma unroll
            for (int ni = 0; ni < 4; ni++)
                *(float2*)(rr2 + ni * 8) = make_float2(acc[mi][ni][2], acc[mi][ni][3]);
        }
        __syncthreads();

        // ---- cell update: 1 (b,hl) pair per thread ----
        {
            float sg[4];
#pragma unroll
            for (int g = 0; g < 4; g++) {
                int n = g * 8 + hlp;
                float s0 = 0.f;
#pragma unroll
                for (int k2 = 0; k2 < 8; k2++)
                    s0 += red[(k2 * 64 + bp) * 32 + n];
                sg[g] = s0 + xq[g];
            }
            float gi = sigmoidf_(sg[0]);
            float gf = sigmoidf_(sg[1]);
            float gg = tanhf(sg[2]);
            float go = sigmoidf_(sg[3]);
            float cn = gf * c_sm[tid] + gi * gg;
            c_sm[tid] = cn;
            float hn = go * tanhf(cn);
            if (t < SEQLEN - 1) {
                g_hh[(t + 1) & 1][bp * HSZ + h0 + hlp] = __float2half_rn(hn);
            } else {
                out[bp * HSZ + h0 + hlp] = hn;
                out[BATCHSZ * HSZ + bp * HSZ + h0 + hlp] = cn;
            }
        }

        if (t < SEQLEN - 1) {
            GRID_BARRIER((t + 2) * NBLK);
        }
    }
}

// ================= launch =================
extern "C" void kernel_launch(void* const* d_in, const int* in_sizes, int n_in,
                              void* d_out, int out_size) {
    const float* x    = (const float*)d_in[0];
    const float* Wx   = (const float*)d_in[1];
    const float* Wh   = (const float*)d_in[2];
    const float* bias = (const float*)d_in[3];
    float* out = (float*)d_out;

    cudaFuncSetAttribute(lstm_scan, cudaFuncAttributeMaxDynamicSharedMemorySize, SCAN_SMEM);
    cudaFuncSetAttribute(gemm_x_mma, cudaFuncAttributeMaxDynamicSharedMemorySize, GX_SMEM);

    init_bar<<<1, 32>>>();                 // zero barrier counter (every graph replay)
    prep<<<40960, 256>>>(x, Wx, Wh);       // slot 1

    dim3 g1(GHSZ / 128, (BATCHSZ * SEQLEN) / 128);
    gemm_x_mma<<<g1, 256, GX_SMEM>>>(bias);  // slot 2

    lstm_scan<<<NBLK, STHR, SCAN_SMEM>>>(out);  // slot 3 -> ncu capture window
}

// round 17
// speedup vs baseline: 1.1623x; 1.0918x over previous
#include <cuda_runtime.h>
#include <cuda_bf16.h>
#include <cuda_fp16.h>
#include <math.h>
#include <cstdint>

#define BATCHSZ 64
#define SEQLEN  512
#define ISZ     512
#define HSZ     1024
#define GHSZ    4096
#define NBLK    128

// ================= device scratch =================
__device__ float g_xg[(size_t)SEQLEN * BATCHSZ * GHSZ];      // [S][B][4H]
__device__ unsigned g_bar;
__device__ __align__(16) __half g_xhi[(size_t)BATCHSZ * SEQLEN * ISZ];
__device__ __align__(16) __half g_wthi[(size_t)GHSZ * ISZ];   // WxT [n][k] fp16
__device__ __align__(16) __half g_whh[(size_t)NBLK * 32 * HSZ];   // Wh fp16 [blk][nl][k]
__device__ __align__(16) __half g_hh[2][BATCHSZ * HSZ];           // h fp16, double buffered

// ================= helpers =================
__device__ __forceinline__ uint32_t smem_u32(const void* p) {
    uint32_t a;
    asm("{ .reg .u64 t; cvta.to.shared.u64 t, %1; cvt.u32.u64 %0, t; }" : "=r"(a) : "l"(p));
    return a;
}

#define LDSM_X4(r0, r1, r2, r3, addr)                                        \
    asm volatile("ldmatrix.sync.aligned.m8n8.x4.shared.b16 {%0,%1,%2,%3}, [%4];" \
                 : "=r"(r0), "=r"(r1), "=r"(r2), "=r"(r3) : "r"(addr))

#define MMAF16(c, a, b)                                                      \
    asm volatile("mma.sync.aligned.m16n8k16.row.col.f32.f16.f16.f32 "        \
                 "{%0,%1,%2,%3}, {%4,%5,%6,%7}, {%8,%9}, {%0,%1,%2,%3};"     \
                 : "+f"((c)[0]), "+f"((c)[1]), "+f"((c)[2]), "+f"((c)[3])    \
                 : "r"((a)[0]), "r"((a)[1]), "r"((a)[2]), "r"((a)[3]),       \
                   "r"((b)[0]), "r"((b)[1]))

#define CP_ASYNC16(smaddr, gptr)                                             \
    asm volatile("cp.async.cg.shared.global [%0], [%1], 16;"                 \
                 :: "r"(smaddr), "l"(__cvta_generic_to_global(gptr)) : "memory")
#define CP_COMMIT()  asm volatile("cp.async.commit_group;" ::: "memory")
#define CP_WAIT0()   asm volatile("cp.async.wait_group 0;" ::: "memory")
#define CP_WAIT1()   asm volatile("cp.async.wait_group 1;" ::: "memory")

__device__ __forceinline__ float sigmoidf_(float v) { return 1.f / (1.f + __expf(-v)); }

// ================= fused prep kernel (also zeroes the grid barrier) =================
__global__ void prep(const float* __restrict__ x,
                     const float* __restrict__ Wx,
                     const float* __restrict__ Wh) {
    int bid = blockIdx.x;
    if (bid == 0 && threadIdx.x == 0) g_bar = 0u;   // every graph replay
    if (bid < 16384) {
        size_t i = ((size_t)bid * 256 + threadIdx.x) * 4;
        float4 v = *(const float4*)(x + i);
        __half2* hp = (__half2*)(g_xhi + i);
        hp[0] = __half2(__float2half_rn(v.x), __float2half_rn(v.y));
        hp[1] = __half2(__float2half_rn(v.z), __float2half_rn(v.w));
    } else if (bid < 24576) {
        int i = (bid - 16384) * 256 + threadIdx.x;   // 4*512*1024
        int g = i >> 19;
        int r = i & 524287;
        int k = r >> 10;
        int h = r & 1023;
        g_wthi[(size_t)(g * HSZ + h) * ISZ + k] = __float2half_rn(Wx[i]);
    } else {
        int d = (bid - 24576) * 256 + threadIdx.x;   // 4M
        int k   = d & 1023;
        int nl  = (d >> 10) & 31;
        int blk = d >> 15;
        int g   = nl >> 3;
        int h   = blk * 8 + (nl & 7);
        g_whh[d] = __float2half_rn(Wh[(size_t)g * HSZ * HSZ + (size_t)k * HSZ + h]);
    }
}

// ================= phase 1: pipelined mma.sync GEMM, 1 product (fp16) =================
#define TILE_B   8192
#define GX_STAGE 16384
#define GX_SMEM  (3 * GX_STAGE)

__global__ __launch_bounds__(256, 2) void gemm_x_mma(const float* __restrict__ bias) {
    extern __shared__ char gsm[];

    const int tid  = threadIdx.x;
    const int lane = tid & 31;
    const int wid  = tid >> 5;
    const int wm   = (wid & 1) * 64;
    const int wn   = (wid >> 1) * 32;
    const int m0   = blockIdx.y * 128;
    const int j0   = blockIdx.x * 128;

    const uint32_t sb = smem_u32(gsm);
    const int g = lane >> 3;
    const int r = lane & 7;

    float acc[4][4][4];
#pragma unroll
    for (int mi = 0; mi < 4; mi++)
#pragma unroll
        for (int ni = 0; ni < 4; ni++)
#pragma unroll
            for (int e = 0; e < 4; e++) acc[mi][ni][e] = 0.f;

#define GX_STAGE_CHUNK(s) do {                                               \
    int k0_ = (s) * 32;                                                      \
    uint32_t db_ = sb + ((s) % 3) * GX_STAGE;                                \
    _Pragma("unroll")                                                        \
    for (int l_ = 0; l_ < 2; l_++) {                                         \
        int u_ = tid + l_ * 256;                                             \
        int row_ = u_ >> 2, ch_ = u_ & 3;                                    \
        uint32_t so_ = row_ * 64 + ((ch_ ^ ((row_ >> 1) & 3)) << 4);         \
        size_t ga_ = (size_t)(m0 + row_) * ISZ + k0_ + ch_ * 8;              \
        size_t gb_ = (size_t)(j0 + row_) * ISZ + k0_ + ch_ * 8;              \
        CP_ASYNC16(db_ + so_,          g_xhi + ga_);                         \
        CP_ASYNC16(db_ + TILE_B + so_, g_wthi + gb_);                        \
    }                                                                        \
} while (0)

#pragma unroll
    for (int ps = 0; ps < 2; ps++) {
        GX_STAGE_CHUNK(ps);
        CP_COMMIT();
    }

    for (int s = 0; s < 16; s++) {
        CP_WAIT1();
        __syncthreads();

        const uint32_t stb = sb + (s % 3) * GX_STAGE;
#pragma unroll
        for (int s2 = 0; s2 < 2; s2++) {
            uint32_t ahi[4][4];
#pragma unroll
            for (int mi = 0; mi < 4; mi++) {
                int row = wm + mi * 16 + (g & 1) * 8 + r;
                int ch  = (s2 * 2 + (g >> 1)) ^ ((row >> 1) & 3);
                uint32_t ad = stb + row * 64 + ch * 16;
                LDSM_X4(ahi[mi][0], ahi[mi][1], ahi[mi][2], ahi[mi][3], ad);
            }
            uint32_t bhi[4][2];
#pragma unroll
            for (int nb = 0; nb < 2; nb++) {
                int row = wn + nb * 16 + (g >> 1) * 8 + r;
                int ch  = (s2 * 2 + (g & 1)) ^ ((row >> 1) & 3);
                uint32_t bd = stb + TILE_B + row * 64 + ch * 16;
                LDSM_X4(bhi[nb * 2][0], bhi[nb * 2][1],
                        bhi[nb * 2 + 1][0], bhi[nb * 2 + 1][1], bd);
            }
#pragma unroll
            for (int mi = 0; mi < 4; mi++)
#pragma unroll
                for (int ni = 0; ni < 4; ni++)
                    MMAF16(acc[mi][ni], ahi[mi], bhi[ni]);
        }

        if (s + 2 < 16) GX_STAGE_CHUNK(s + 2);
        CP_COMMIT();
    }

    const int r4 = lane >> 2;
    const int c2 = (lane & 3) * 2;
#pragma unroll
    for (int mi = 0; mi < 4; mi++) {
        int mA = m0 + wm + mi * 16 + r4;
        int mB = mA + 8;
        size_t baseA = (((size_t)((mA & 511) * BATCHSZ + (mA >> 9))) << 12);
        size_t baseB = (((size_t)((mB & 511) * BATCHSZ + (mB >> 9))) << 12);
#pragma unroll
        for (int ni = 0; ni < 4; ni++) {
            int n = j0 + wn + ni * 8 + c2;
            float2 bv = *(const float2*)(bias + n);
            float2 vA = make_float2(acc[mi][ni][0] + bv.x, acc[mi][ni][1] + bv.y);
            float2 vB = make_float2(acc[mi][ni][2] + bv.x, acc[mi][ni][3] + bv.y);
            *(float2*)(g_xg + baseA + n) = vA;
            *(float2*)(g_xg + baseB + n) = vB;
        }
    }
}

// ================= phase 2: persistent mma LSTM scan (unchanged from R16) =================
// smem: W tiles [16 k64-slabs][32n x 128B]   = 64KB at 0
//       h ring  [2 buf][64KB (64r x 1024B)]  = 128KB at 65536
//       red     [512 rows x 32 floats] = 64KB, ALIASES ring buf0 (safe: see syncs)
//       c_sm    [512] float                          at 196608
#define WOFF 0
#define HOFF 65536
#define COFF 196608
#define SCAN_SMEM (196608 + 2048)
#define STHR 512

#define GRID_BARRIER(target) do {                                            \
    __syncthreads();                                                         \
    if (tid == 0) {                                                          \
        __threadfence();                                                     \
        atomicAdd(&g_bar, 1u);                                               \
        unsigned v_;                                                         \
        do {                                                                 \
            asm volatile("ld.acquire.gpu.u32 %0, [%1];" : "=r"(v_) : "l"(&g_bar) : "memory"); \
        } while (v_ < (unsigned)(target));                                   \
    }                                                                        \
    __syncthreads();                                                         \
} while (0)

__global__ __launch_bounds__(STHR, 1) void lstm_scan(float* __restrict__ out) {
    extern __shared__ char sm[];
    const uint32_t sb = smem_u32(sm);
    float* c_sm = (float*)(sm + COFF);
    float* red  = (float*)(sm + HOFF);    // 64KB, aliases ring buffer 0

    const int tid  = threadIdx.x;
    const int blk  = blockIdx.x;
    const int h0   = blk * 8;
    const int lane = tid & 31, wid = tid >> 5;
    const int wm   = wid & 1;             // M half (batches 0-31 / 32-63)
    const int ks   = wid >> 1;            // k64 slot within k512 slab (0..7)
    const int g8   = lane >> 3, r8 = lane & 7;

    // zero own h columns (buf 0) + c
    {
        int b = tid >> 3, hl = tid & 7;
        g_hh[0][b * HSZ + h0 + hl] = __float2half(0.f);
        c_sm[tid] = 0.f;
    }

    // load W into smem once: 4096 16B-chunks / 512 threads (fp16)
#pragma unroll
    for (int l = 0; l < 8; l++) {
        int u = tid + l * STHR;
        int tile = u >> 8;                // k64 tile 0..15
        int c = u & 255;
        int row = c >> 3, cc = c & 7;
        const __half* src = g_whh + ((size_t)(blk * 32 + row) * HSZ + tile * 64 + cc * 8);
        *(uint4*)(sm + WOFF + tile * 4096 + row * 128 + ((cc ^ (row & 7)) << 4))
            = *(const uint4*)src;
    }

    GRID_BARRIER(NBLK);   // zeros + W visible

    // epilogue mapping: thread owns 1 (b,hl) pair
    const int bp = tid >> 3, hlp = tid & 7;

    // h-slab staging: k512 slab (64 rows x 1024B = 64KB) -> ring buffer slab&1
#define SCAN_STAGE(slab) do {                                                \
    uint32_t hb_ = sb + HOFF + ((slab) & 1) * 65536;                         \
    _Pragma("unroll")                                                        \
    for (int l_ = 0; l_ < 8; l_++) {                                         \
        int u_ = tid + l_ * STHR;                                            \
        int row_ = u_ >> 6, cc_ = u_ & 63;                                   \
        uint32_t d_ = hb_ + row_ * 1024 + ((cc_ ^ (row_ & 7)) << 4);         \
        CP_ASYNC16(d_, hh + row_ * HSZ + (slab) * 512 + cc_ * 8);            \
    }                                                                        \
} while (0)

    for (int t = 0; t < SEQLEN; t++) {
        const __half* hh = g_hh[t & 1];

        // prefetch xg for epilogue
        float xq[4];
        {
            size_t base = (((size_t)(t * BATCHSZ + bp)) << 12) + h0 + hlp;
#pragma unroll
            for (int g = 0; g < 4; g++) xq[g] = __ldcs(&g_xg[base + (size_t)g * HSZ]);
        }

        float acc[2][4][4];
#pragma unroll
        for (int mi = 0; mi < 2; mi++)
#pragma unroll
            for (int ni = 0; ni < 4; ni++)
#pragma unroll
                for (int e = 0; e < 4; e++) acc[mi][ni][e] = 0.f;

        // prologue: slab 0
        SCAN_STAGE(0);
        CP_COMMIT();

#pragma unroll
        for (int s = 0; s < 2; s++) {
            if (s == 0) {
                SCAN_STAGE(1);
                CP_COMMIT();
                CP_WAIT1();        // slab 0 landed
            } else {
                CP_WAIT0();        // slab 1 landed
            }
            __syncthreads();       // block-wide visibility of slab s

            // ---- compute slab s: this warp's k16s = s*32 + ks*4 + {0..3} ----
            uint32_t hb = sb + HOFF + (s & 1) * 65536;
#pragma unroll
            for (int half = 0; half < 2; half++) {
                uint32_t ah[2][2][4], bh[2][4][2];
#pragma unroll
                for (int mi = 0; mi < 2; mi++) {
                    int row = wm * 32 + mi * 16 + (g8 & 1) * 8 + r8;
#pragma unroll
                    for (int kc = 0; kc < 2; kc++) {
                        int kks = ks * 4 + half * 2 + kc;      // k16 within slab (0..31)
                        int cc  = kks * 2 + (g8 >> 1);          // 16B chunk in 1024B row
                        uint32_t ad = hb + row * 1024 + (((cc ^ (row & 7))) << 4);
                        LDSM_X4(ah[mi][kc][0], ah[mi][kc][1], ah[mi][kc][2], ah[mi][kc][3], ad);
                    }
                }
#pragma unroll
                for (int kc = 0; kc < 2; kc++) {
                    int kk = s * 32 + ks * 4 + half * 2 + kc;   // global k16 (0..63)
                    int sW = kk >> 2, c4 = kk & 3;
#pragma unroll
                    for (int nb = 0; nb < 2; nb++) {
                        int row = nb * 16 + (g8 >> 1) * 8 + r8;
                        int cc2 = c4 * 2 + (g8 & 1);
                        uint32_t bd = sb + WOFF + sW * 4096 + row * 128 + (((cc2 ^ (row & 7))) << 4);
                        LDSM_X4(bh[kc][nb * 2][0], bh[kc][nb * 2][1],
                                bh[kc][nb * 2 + 1][0], bh[kc][nb * 2 + 1][1], bd);
                    }
                }
#pragma unroll
                for (int kc = 0; kc < 2; kc++)
#pragma unroll
                    for (int mi = 0; mi < 2; mi++)
#pragma unroll
                        for (int ni = 0; ni < 4; ni++)
                            MMAF16(acc[mi][ni], ah[mi][kc], bh[kc][ni]);
            }
            // no trailing sync: within a step no buffer is restaged; buf0 reads
            // are ordered before red writes by slab 1's top-of-iteration sync.
        }

        // ---- write K-partials to red (aliases buf0; safe per sync above) ----
#pragma unroll
        for (int mi = 0; mi < 2; mi++) {
            int b = wm * 32 + mi * 16 + (lane >> 2);
            int n = (lane & 3) * 2;
            float* rr = red + (ks * 64 + b) * 32 + n;
#pragma unroll
            for (int ni = 0; ni < 4; ni++)
                *(float2*)(rr + ni * 8) = make_float2(acc[mi][ni][0], acc[mi][ni][1]);
            float* rr2 = red + (ks * 64 + b + 8) * 32 + n;
#pragma unroll
            for (int ni = 0; ni < 4; ni++)
                *(float2*)(rr2 + ni * 8) = make_float2(acc[mi][ni][2], acc[mi][ni][3]);
        }
        __syncthreads();

        // ---- cell update: 1 (b,hl) pair per thread ----
        {
            float sg[4];
#pragma unroll
            for (int g = 0; g < 4; g++) {
                int n = g * 8 + hlp;
                float s0 = 0.f;
#pragma unroll
                for (int k2 = 0; k2 < 8; k2++)
                    s0 += red[(k2 * 64 + bp) * 32 + n];
                sg[g] = s0 + xq[g];
            }
            float gi = sigmoidf_(sg[0]);
            float gf = sigmoidf_(sg[1]);
            float gg = tanhf(sg[2]);
            float go = sigmoidf_(sg[3]);
            float cn = gf * c_sm[tid] + gi * gg;
            c_sm[tid] = cn;
            float hn = go * tanhf(cn);
            if (t < SEQLEN - 1) {
                g_hh[(t + 1) & 1][bp * HSZ + h0 + hlp] = __float2half_rn(hn);
            } else {
                out[bp * HSZ + h0 + hlp] = hn;
                out[BATCHSZ * HSZ + bp * HSZ + h0 + hlp] = cn;
            }
        }

        if (t < SEQLEN - 1) {
            GRID_BARRIER((t + 2) * NBLK);
        }
    }
}

// ================= launch =================
extern "C" void kernel_launch(void* const* d_in, const int* in_sizes, int n_in,
                              void* d_out, int out_size) {
    const float* x    = (const float*)d_in[0];
    const float* Wx   = (const float*)d_in[1];
    const float* Wh   = (const float*)d_in[2];
    const float* bias = (const float*)d_in[3];
    float* out = (float*)d_out;

    cudaFuncSetAttribute(lstm_scan, cudaFuncAttributeMaxDynamicSharedMemorySize, SCAN_SMEM);
    cudaFuncSetAttribute(gemm_x_mma, cudaFuncAttributeMaxDynamicSharedMemorySize, GX_SMEM);

    prep<<<40960, 256>>>(x, Wx, Wh);       // slot 0 (also zeroes g_bar)

    dim3 g1(GHSZ / 128, (BATCHSZ * SEQLEN) / 128);
    gemm_x_mma<<<g1, 256, GX_SMEM>>>(bias);  // slot 1

    lstm_scan<<<NBLK, STHR, SCAN_SMEM>>>(out);  // slot 2
}